// round 8
// baseline (speedup 1.0000x reference)
#include <cuda_runtime.h>
#include <cstdint>

#define T_LEN   16384
#define T_MASK  16383
#define L_HALF  50
#define NMN     449
#define NK      11
#define NOUT    16284      // T - 2*L
#define TILE_T  256
#define THREADS 256
#define CHUNK   64
#define HALF0   225        // pairs [0,225) -> half 0, [225,449) -> half 1

// -------- compile-time (m,n) pair table (reference enumeration order) --------
struct MNTab { short m[NMN]; short n[NMN]; };
constexpr MNTab make_mn() {
    MNTab t{};
    int c = 0;
    for (int m = -25; m <= 25; ++m)
        for (int n = -25; n <= 25; ++n) {
            int p = m * n; if (p < 0) p = -p;
            if (p <= 25) { t.m[c] = (short)m; t.n[c] = (short)n; ++c; }
        }
    return t;
}
__constant__ MNTab c_mn = make_mn();

// -------- device scratch (no allocations allowed) --------
// per pair layout: [0]=cp, [1..11]=C1_j, [12..22]=C2_j
__device__ float4 g_coef[2][NMN][23];
// partial results: [half][batch*NOUT] complex (float2)
__device__ float2 g_part[2][2 * NOUT];

// -------- packed f32x2 helpers (Blackwell FFMA2) --------
static __device__ __forceinline__ unsigned long long f2fma(unsigned long long a, unsigned long long b, unsigned long long c) {
    unsigned long long d;
    asm("fma.rn.f32x2 %0, %1, %2, %3;" : "=l"(d) : "l"(a), "l"(b), "l"(c));
    return d;
}
static __device__ __forceinline__ unsigned long long f2mul(unsigned long long a, unsigned long long b) {
    unsigned long long d;
    asm("mul.rn.f32x2 %0, %1, %2;" : "=l"(d) : "l"(a), "l"(b));
    return d;
}
static __device__ __forceinline__ unsigned long long pk2(float lo, float hi) {
    unsigned long long d;
    asm("mov.b64 %0, {%1, %2};" : "=l"(d) : "f"(lo), "f"(hi));
    return d;
}
static __device__ __forceinline__ float2 up2(unsigned long long v) {
    float2 r;
    asm("mov.b64 {%0, %1}, %2;" : "=f"(r.x), "=f"(r.y) : "l"(v));
    return r;
}
static __device__ __forceinline__ unsigned long long ng2(unsigned long long v) {
    return v ^ 0x8000000080000000ULL;
}

// -------- pack coefficients: select batch row, fold power factors, dual layout --------
__global__ void sopbc_pack(const float* __restrict__ ti,
                           const float* __restrict__ pbcr, const float* __restrict__ pbci,
                           const float* __restrict__ c1r,  const float* __restrict__ c1i,
                           const float* __restrict__ c2r,  const float* __restrict__ c2i) {
    int idx = blockIdx.x * blockDim.x + threadIdx.x;
    if (idx >= 2 * NMN) return;
    int b = idx / NMN;
    int p = idx % NMN;

    int xi = (int)(ti[b * 4 + 2] / 2.0e9f);
    int ind = 0;
    if (xi == 20) ind = 0;
    else if (xi == 40) ind = 1;
    else if (xi == 80) ind = 2;
    else if (xi == 160) ind = 3;

    float P  = exp10f(ti[b * 4 + 0] * 0.1f);
    float sp = sqrtf(P);
    float f3 = sp * sp * sp;
    float f5 = f3 * sp * sp;

    float4* dst = &g_coef[b][p][0];
    float cpr = f3 * pbcr[ind * NMN + p];
    float cpi = f3 * pbci[ind * NMN + p];
    dst[0] = make_float4(cpr, cpi, -cpi, cpr);

    int cb = ind * (NMN * NK) + p * NK;
#pragma unroll
    for (int j = 0; j < NK; ++j) {
        float u1 = f5 * c1r[cb + j], w1 = f5 * c1i[cb + j];
        float u2 = f5 * c2r[cb + j], w2 = f5 * c2i[cb + j];
        dst[1 + j]  = make_float4(u1, w1, -w1, u1);   // A * C1
        dst[12 + j] = make_float4(u2, w2, w2, -u2);   // conj(A) * C2
    }
}

// -------- main kernel --------
// grid = (64 t-tiles, 2 batches, 2 pair-halves); 256 threads.
//   warps 0-3 (g=0): compute A, cp-acc, G1 (A*C1), write partial
//   warps 4-7 (g=1): compute A, G2 (conj(A)*C2), merge via smem
// Each thread covers t1 = win0+slot and t2 = win0+slot+128 (ILP2, f32x2-packed).
// Each pair-half writes its contribution to g_part[half]; combine kernel sums.
__global__ __launch_bounds__(THREADS, 2)
void sopbc_main(const float* __restrict__ Er, const float* __restrict__ Ei) {
    __shared__ float2 sE[356];
    __shared__ float4 s_cf[CHUNK * 23];
    __shared__ float4 s_red[128];

    const int tid  = threadIdx.x;
    const int slot = tid & 127;
    const int g    = tid >> 7;
    const int b    = blockIdx.y;
    const int h    = blockIdx.z;
    const int bx   = blockIdx.x;
    const int base = b * T_LEN;
    const int win0 = bx * TILE_T;

    const int PSTART = h ? HALF0 : 0;
    const int PEND   = h ? NMN   : HALF0;

    for (int i = tid; i < 356; i += THREADS) {
        int t = (win0 + i) & T_MASK;
        sE[i] = make_float2(Er[base + t], Ei[base + t]);
    }

    unsigned long long X[NK], Y[NK];
    unsigned long long A0 = 0ull, A1 = 0ull;
#pragma unroll
    for (int j = 0; j < NK; ++j) { X[j] = Y[j] = 0ull; }

    const int i1 = slot + L_HALF;
    const int i2 = slot + 128 + L_HALF;

    const float4* gsrc = &g_coef[b][0][0];

    for (int p0 = PSTART; p0 < PEND; p0 += CHUNK) {
        const int np = (PEND - p0 < CHUNK) ? (PEND - p0) : CHUNK;
        __syncthreads();
        {
            const float4* src = gsrc + p0 * 23;
            const int cnt = np * 23;
            for (int i = tid; i < cnt; i += THREADS) s_cf[i] = src[i];
        }
        __syncthreads();

        if (g == 0) {
            for (int p = 0; p < np; ++p) {
                const int m = c_mn.m[p0 + p], n = c_mn.n[p0 + p];
                float2 av1 = sE[i1 - n],     av2 = sE[i2 - n];
                float2 bv1 = sE[i1 - m - n], bv2 = sE[i2 - m - n];
                float2 cv1 = sE[i1 - m],     cv2 = sE[i2 - m];

                unsigned long long ar = pk2(av1.x, av2.x), ai = pk2(av1.y, av2.y);
                unsigned long long br = pk2(bv1.x, bv2.x), bi = pk2(bv1.y, bv2.y);
                unsigned long long cr = pk2(cv1.x, cv2.x), ci = pk2(cv1.y, cv2.y);

                unsigned long long ur  = f2fma(ai, bi, f2mul(ar, br));
                unsigned long long ui  = f2fma(ai, br, f2mul(ng2(ar), bi));
                unsigned long long Arr = f2fma(ng2(ui), ci, f2mul(ur, cr));
                unsigned long long Aii = f2fma(ur, ci, f2mul(ui, cr));

                float2 arp = up2(Arr), aip = up2(Aii);
                unsigned long long R1 = pk2(arp.x, arp.x), I1 = pk2(aip.x, aip.x);
                unsigned long long R2 = pk2(arp.y, arp.y), I2 = pk2(aip.y, aip.y);

                const ulonglong2* cf = reinterpret_cast<const ulonglong2*>(s_cf + p * 23);
                ulonglong2 c0 = cf[0];
                A0 = f2fma(I1, c0.y, f2fma(R1, c0.x, A0));
                A1 = f2fma(I2, c0.y, f2fma(R2, c0.x, A1));
#pragma unroll
                for (int j = 0; j < NK; ++j) {
                    ulonglong2 c = cf[1 + j];
                    X[j] = f2fma(I1, c.y, f2fma(R1, c.x, X[j]));
                    Y[j] = f2fma(I2, c.y, f2fma(R2, c.x, Y[j]));
                }
            }
        } else {
            for (int p = 0; p < np; ++p) {
                const int m = c_mn.m[p0 + p], n = c_mn.n[p0 + p];
                float2 av1 = sE[i1 - n],     av2 = sE[i2 - n];
                float2 bv1 = sE[i1 - m - n], bv2 = sE[i2 - m - n];
                float2 cv1 = sE[i1 - m],     cv2 = sE[i2 - m];

                unsigned long long ar = pk2(av1.x, av2.x), ai = pk2(av1.y, av2.y);
                unsigned long long br = pk2(bv1.x, bv2.x), bi = pk2(bv1.y, bv2.y);
                unsigned long long cr = pk2(cv1.x, cv2.x), ci = pk2(cv1.y, cv2.y);

                unsigned long long ur  = f2fma(ai, bi, f2mul(ar, br));
                unsigned long long ui  = f2fma(ai, br, f2mul(ng2(ar), bi));
                unsigned long long Arr = f2fma(ng2(ui), ci, f2mul(ur, cr));
                unsigned long long Aii = f2fma(ur, ci, f2mul(ui, cr));

                float2 arp = up2(Arr), aip = up2(Aii);
                unsigned long long R1 = pk2(arp.x, arp.x), I1 = pk2(aip.x, aip.x);
                unsigned long long R2 = pk2(arp.y, arp.y), I2 = pk2(aip.y, aip.y);

                const ulonglong2* cf = reinterpret_cast<const ulonglong2*>(s_cf + p * 23);
#pragma unroll
                for (int j = 0; j < NK; ++j) {
                    ulonglong2 c = cf[12 + j];
                    X[j] = f2fma(I1, c.y, f2fma(R1, c.x, X[j]));
                    Y[j] = f2fma(I2, c.y, f2fma(R2, c.x, Y[j]));
                }
            }
        }
    }

    // ---- epilogue ----
    if (g == 1) {
        // partial: sum_j Q * G2  (Q = E^2 at t-k)
        float pr1 = 0.f, pi1 = 0.f, pr2 = 0.f, pi2 = 0.f;
#pragma unroll
        for (int j = 0; j < NK; ++j) {
            float2 e1 = sE[i1 + 5 - j];
            float Qr1 = e1.x * e1.x - e1.y * e1.y;
            float Qi1 = 2.f * e1.x * e1.y;
            float2 g2 = up2(X[j]);
            pr1 += Qr1 * g2.x - Qi1 * g2.y;
            pi1 += Qr1 * g2.y + Qi1 * g2.x;

            float2 e2 = sE[i2 + 5 - j];
            float Qr2 = e2.x * e2.x - e2.y * e2.y;
            float Qi2 = 2.f * e2.x * e2.y;
            float2 h2 = up2(Y[j]);
            pr2 += Qr2 * h2.x - Qi2 * h2.y;
            pi2 += Qr2 * h2.y + Qi2 * h2.x;
        }
        s_red[slot] = make_float4(pr1, pi1, pr2, pi2);
    }
    __syncthreads();
    if (g == 0) {
        float4 r = s_red[slot];
        float2* dst = &g_part[h][b * NOUT];
        // t1 (always valid: max to1 = 63*256+127 = 16255 < 16284)
        {
            float2 cp = up2(A0);
            float er = cp.x + r.x, eim = cp.y + r.y;
            if (h == 0) { float2 e0 = sE[i1]; er += e0.x; eim += e0.y; }
#pragma unroll
            for (int j = 0; j < NK; ++j) {
                float2 e  = sE[i1 + 5 - j];
                float Iv  = e.x * e.x + e.y * e.y;
                float2 g1 = up2(X[j]);
                er  += Iv * g1.x;
                eim += Iv * g1.y;
            }
            dst[win0 + slot] = make_float2(er, eim);
        }
        // t2 (guarded)
        {
            int to = win0 + slot + 128;
            if (to < NOUT) {
                float2 cp = up2(A1);
                float er = cp.x + r.z, eim = cp.y + r.w;
                if (h == 0) { float2 e0 = sE[i2]; er += e0.x; eim += e0.y; }
#pragma unroll
                for (int j = 0; j < NK; ++j) {
                    float2 e  = sE[i2 + 5 - j];
                    float Iv  = e.x * e.x + e.y * e.y;
                    float2 g1 = up2(Y[j]);
                    er  += Iv * g1.x;
                    eim += Iv * g1.y;
                }
                dst[to] = make_float2(er, eim);
            }
        }
    }
}

// -------- combine: out = part[0] + part[1] --------
__global__ void sopbc_combine(float* __restrict__ out) {
    int i = blockIdx.x * blockDim.x + threadIdx.x;
    if (i >= 2 * NOUT) return;
    float2 a = g_part[0][i];
    float2 c = g_part[1][i];
    reinterpret_cast<float2*>(out)[i] = make_float2(a.x + c.x, a.y + c.y);
}

extern "C" void kernel_launch(void* const* d_in, const int* in_sizes, int n_in,
                              void* d_out, int out_size) {
    const float* Er   = (const float*)d_in[0];
    const float* Ei   = (const float*)d_in[1];
    const float* ti   = (const float*)d_in[2];
    const float* pbcr = (const float*)d_in[3];
    const float* pbci = (const float*)d_in[4];
    const float* c1r  = (const float*)d_in[5];
    const float* c1i  = (const float*)d_in[6];
    const float* c2r  = (const float*)d_in[7];
    const float* c2i  = (const float*)d_in[8];
    float* out = (float*)d_out;

    sopbc_pack<<<(2 * NMN + 127) / 128, 128>>>(ti, pbcr, pbci, c1r, c1i, c2r, c2i);

    dim3 grid(64, 2, 2);
    sopbc_main<<<grid, THREADS>>>(Er, Ei);

    sopbc_combine<<<(2 * NOUT + 255) / 256, 256>>>(out);
}